// round 2
// baseline (speedup 1.0000x reference)
#include <cuda_runtime.h>
#include <cstdint>

#define N_FEAT 512
#define N_HID  16
#define N_CLS  40
#define MAX_NODES 100000
#define MAX_EDGES 3200000
#define SCAN_B    1024
#define MAX_NB    128   // ceil(MAX_NODES/1024) = 98

// ---------------------------------------------------------------------------
// Scratch (allocation-free: __device__ globals)
// ---------------------------------------------------------------------------
__device__ float  g_support1[MAX_NODES * N_HID];   // X @ W1
__device__ float  g_h[MAX_NODES * N_HID];          // relu(conv1)
__device__ float2 g_ebuf[MAX_EDGES];               // dst-ordered (src_bits, w)
__device__ int    g_deg[MAX_NODES];
__device__ int    g_rowptr[MAX_NODES];
__device__ int    g_cursor[MAX_NODES];
__device__ int    g_blksum[MAX_NB];

#define FMA_F32X2(d, a, b, c) \
    asm("fma.rn.f32x2 %0, %1, %2, %3;" : "=l"(d) : "l"(a), "l"(b), "l"(c))

// ---------------------------------------------------------------------------
// CSR build: zero degrees
// ---------------------------------------------------------------------------
__global__ void zero_deg_kernel(int n) {
    int i = blockIdx.x * blockDim.x + threadIdx.x;
    if (i < n) g_deg[i] = 0;
}

// histogram of dst
__global__ __launch_bounds__(256) void hist_kernel(const int* __restrict__ dst, int nEdges) {
    int e = blockIdx.x * blockDim.x + threadIdx.x;
    if (e < nEdges) atomicAdd(&g_deg[dst[e]], 1);
}

// block-local exclusive scan of deg -> rowptr(partial), blksum[b] = block total
__global__ __launch_bounds__(SCAN_B) void scanA_kernel(int n) {
    __shared__ int s[SCAN_B];
    int tid = threadIdx.x;
    int i = blockIdx.x * SCAN_B + tid;
    int v = (i < n) ? g_deg[i] : 0;
    s[tid] = v;
    __syncthreads();
    #pragma unroll
    for (int off = 1; off < SCAN_B; off <<= 1) {
        int t = (tid >= off) ? s[tid - off] : 0;
        __syncthreads();
        s[tid] += t;
        __syncthreads();
    }
    if (i < n) g_rowptr[i] = s[tid] - v;          // exclusive
    if (tid == SCAN_B - 1) g_blksum[blockIdx.x] = s[tid];
}

// exclusive scan of block sums (single block)
__global__ __launch_bounds__(MAX_NB) void scanB_kernel(int nb) {
    __shared__ int s[MAX_NB];
    int tid = threadIdx.x;
    int v = (tid < nb) ? g_blksum[tid] : 0;
    s[tid] = v;
    __syncthreads();
    #pragma unroll
    for (int off = 1; off < MAX_NB; off <<= 1) {
        int t = (tid >= off) ? s[tid - off] : 0;
        __syncthreads();
        s[tid] += t;
        __syncthreads();
    }
    if (tid < nb) g_blksum[tid] = s[tid] - v;
}

// add block offsets; init cursor = rowptr
__global__ __launch_bounds__(256) void scanC_kernel(int n) {
    int i = blockIdx.x * blockDim.x + threadIdx.x;
    if (i >= n) return;
    int r = g_rowptr[i] + g_blksum[i >> 10];
    g_rowptr[i] = r;
    g_cursor[i] = r;
}

// scatter edges into dst buckets as packed (src_bits, w)
__global__ __launch_bounds__(256) void scatter_kernel(
    const int* __restrict__ src, const int* __restrict__ dst,
    const float* __restrict__ ew, int nEdges)
{
    int e = blockIdx.x * blockDim.x + threadIdx.x;
    if (e >= nEdges) return;
    int d = dst[e];
    int pos = atomicAdd(&g_cursor[d], 1);
    g_ebuf[pos] = make_float2(__int_as_float(src[e]), ew[e]);
}

// ---------------------------------------------------------------------------
// support1 = X @ W1   [nNodes,512] @ [512,16], packed f32x2 FMA
// ---------------------------------------------------------------------------
__global__ __launch_bounds__(256) void gemm1_kernel(
    const float* __restrict__ X, const float* __restrict__ W1, int nNodes)
{
    __shared__ __align__(16) float sW[N_FEAT * N_HID];  // 32 KB
    for (int i = threadIdx.x; i < N_FEAT * N_HID; i += blockDim.x)
        sW[i] = W1[i];
    __syncthreads();

    int row = blockIdx.x * blockDim.x + threadIdx.x;
    if (row >= nNodes) return;

    const float4* xr = reinterpret_cast<const float4*>(X + (size_t)row * N_FEAT);

    unsigned long long acc[8];
    #pragma unroll
    for (int p = 0; p < 8; p++) acc[p] = 0ULL;

    #pragma unroll 2
    for (int k4 = 0; k4 < N_FEAT / 4; k4++) {
        float4 xv = xr[k4];
        #pragma unroll
        for (int t = 0; t < 4; t++) {
            float xs = (t == 0) ? xv.x : (t == 1) ? xv.y : (t == 2) ? xv.z : xv.w;
            unsigned long long xx;
            asm("mov.b64 %0, {%1, %1};" : "=l"(xx) : "f"(xs));
            const float* wrow = sW + (k4 * 4 + t) * N_HID;
            #pragma unroll
            for (int q = 0; q < 2; q++) {
                ulonglong2 w0 = *reinterpret_cast<const ulonglong2*>(wrow + q * 8);
                FMA_F32X2(acc[q * 4 + 0], xx, w0.x, acc[q * 4 + 0]);
                FMA_F32X2(acc[q * 4 + 1], xx, w0.y, acc[q * 4 + 1]);
                ulonglong2 w1 = *reinterpret_cast<const ulonglong2*>(wrow + q * 8 + 4);
                FMA_F32X2(acc[q * 4 + 2], xx, w1.x, acc[q * 4 + 2]);
                FMA_F32X2(acc[q * 4 + 3], xx, w1.y, acc[q * 4 + 3]);
            }
        }
    }

    float* o = g_support1 + (size_t)row * N_HID;
    #pragma unroll
    for (int q = 0; q < 4; q++) {
        ulonglong2 st;
        st.x = acc[q * 2 + 0];
        st.y = acc[q * 2 + 1];
        *reinterpret_cast<ulonglong2*>(o + q * 4) = st;
    }
}

// ---------------------------------------------------------------------------
// Gather accumulate: 16 features into 8 packed f32x2
// ---------------------------------------------------------------------------
__device__ __forceinline__ void gather_accum(
    int node, const float* __restrict__ feat, unsigned long long acc[8])
{
    int beg = g_rowptr[node];
    int deg = g_deg[node];
    const float2* ep = g_ebuf + beg;

    #pragma unroll 4
    for (int i = 0; i < deg; i++) {
        float2 e = __ldg(ep + i);
        int s = __float_as_int(e.x);
        unsigned long long wx2;
        asm("mov.b64 %0, {%1, %1};" : "=l"(wx2) : "f"(e.y));
        const ulonglong2* fp = reinterpret_cast<const ulonglong2*>(feat + (size_t)s * N_HID);
        ulonglong2 f0 = fp[0];
        ulonglong2 f1 = fp[1];
        FMA_F32X2(acc[0], f0.x, wx2, acc[0]);
        FMA_F32X2(acc[1], f0.y, wx2, acc[1]);
        FMA_F32X2(acc[2], f1.x, wx2, acc[2]);
        FMA_F32X2(acc[3], f1.y, wx2, acc[3]);
        const ulonglong2* fq = fp + 2;
        ulonglong2 f2 = fq[0];
        ulonglong2 f3 = fq[1];
        FMA_F32X2(acc[4], f2.x, wx2, acc[4]);
        FMA_F32X2(acc[5], f2.y, wx2, acc[5]);
        FMA_F32X2(acc[6], f3.x, wx2, acc[6]);
        FMA_F32X2(acc[7], f3.y, wx2, acc[7]);
    }
}

// conv1 gather: h = relu(segsum(support1[src]*w) + b1)
__global__ __launch_bounds__(256) void gconv1_kernel(
    const float* __restrict__ b1, int nNodes)
{
    int node = blockIdx.x * blockDim.x + threadIdx.x;
    if (node >= nNodes) return;

    unsigned long long acc[8];
    #pragma unroll
    for (int p = 0; p < 8; p++) acc[p] = 0ULL;
    gather_accum(node, g_support1, acc);

    float* o = g_h + (size_t)node * N_HID;
    #pragma unroll
    for (int p = 0; p < 8; p++) {
        float lo, hi;
        asm("mov.b64 {%0, %1}, %2;" : "=f"(lo), "=f"(hi) : "l"(acc[p]));
        float2 b = *reinterpret_cast<const float2*>(b1 + p * 2);
        lo = fmaxf(lo + b.x, 0.f);
        hi = fmaxf(hi + b.y, 0.f);
        o[p * 2 + 0] = lo;
        o[p * 2 + 1] = hi;
    }
}

// conv2 gather + head: out = log_softmax(segsum(h[src]*w) @ W2 + b2)
__global__ __launch_bounds__(256) void gconv2_head_kernel(
    const float* __restrict__ W2, const float* __restrict__ b2,
    float* __restrict__ out, int nNodes)
{
    __shared__ float sW[N_HID * N_CLS];
    __shared__ float sb[N_CLS];
    for (int i = threadIdx.x; i < N_HID * N_CLS; i += blockDim.x) sW[i] = W2[i];
    for (int i = threadIdx.x; i < N_CLS; i += blockDim.x) sb[i] = b2[i];
    __syncthreads();

    int node = blockIdx.x * blockDim.x + threadIdx.x;
    if (node >= nNodes) return;

    unsigned long long acc[8];
    #pragma unroll
    for (int p = 0; p < 8; p++) acc[p] = 0ULL;
    gather_accum(node, g_h, acc);

    float v[N_HID];
    #pragma unroll
    for (int p = 0; p < 8; p++)
        asm("mov.b64 {%0, %1}, %2;" : "=f"(v[p * 2]), "=f"(v[p * 2 + 1]) : "l"(acc[p]));

    float y[N_CLS];
    #pragma unroll
    for (int c = 0; c < N_CLS; c++) y[c] = sb[c];
    #pragma unroll
    for (int k = 0; k < N_HID; k++) {
        float vk = v[k];
        const float* wr = sW + k * N_CLS;
        #pragma unroll
        for (int c = 0; c < N_CLS; c++)
            y[c] = fmaf(vk, wr[c], y[c]);
    }

    float mx = y[0];
    #pragma unroll
    for (int c = 1; c < N_CLS; c++) mx = fmaxf(mx, y[c]);
    float sum = 0.f;
    #pragma unroll
    for (int c = 0; c < N_CLS; c++) sum += __expf(y[c] - mx);
    float lse = mx + __logf(sum);

    float* o = out + (size_t)node * N_CLS;
    #pragma unroll
    for (int q = 0; q < N_CLS / 4; q++) {
        float4 st = make_float4(y[q * 4 + 0] - lse, y[q * 4 + 1] - lse,
                                y[q * 4 + 2] - lse, y[q * 4 + 3] - lse);
        *reinterpret_cast<float4*>(o + q * 4) = st;
    }
}

// ---------------------------------------------------------------------------
// Launcher
// ---------------------------------------------------------------------------
extern "C" void kernel_launch(void* const* d_in, const int* in_sizes, int n_in,
                              void* d_out, int out_size)
{
    const float* x        = (const float*)d_in[0];
    const int*   edge_src = (const int*)  d_in[1];
    const int*   edge_dst = (const int*)  d_in[2];
    const float* edge_w   = (const float*)d_in[3];
    const float* W1       = (const float*)d_in[4];
    const float* b1       = (const float*)d_in[5];
    const float* W2       = (const float*)d_in[6];
    const float* b2       = (const float*)d_in[7];
    float* out = (float*)d_out;

    int nNodes = in_sizes[0] / N_FEAT;
    int nEdges = in_sizes[1];
    int nb = (nNodes + SCAN_B - 1) / SCAN_B;

    // CSR build
    zero_deg_kernel<<<(nNodes + 255) / 256, 256>>>(nNodes);
    hist_kernel<<<(nEdges + 255) / 256, 256>>>(edge_dst, nEdges);
    scanA_kernel<<<nb, SCAN_B>>>(nNodes);
    scanB_kernel<<<1, MAX_NB>>>(nb);
    scanC_kernel<<<(nNodes + 255) / 256, 256>>>(nNodes);
    scatter_kernel<<<(nEdges + 255) / 256, 256>>>(edge_src, edge_dst, edge_w, nEdges);

    // dense + gathers
    gemm1_kernel<<<(nNodes + 255) / 256, 256>>>(x, W1, nNodes);
    gconv1_kernel<<<(nNodes + 255) / 256, 256>>>(b1, nNodes);
    gconv2_head_kernel<<<(nNodes + 255) / 256, 256>>>(W2, b2, out, nNodes);
}